// round 3
// baseline (speedup 1.0000x reference)
#include <cuda_runtime.h>
#include <math_constants.h>

// Problem constants
#define B 16
#define S 8192
#define D 256
#define D2 512
#define NTOK (B * S)          // 131072 tokens
#define TOK 32                // tokens per score block
#define SCHUNKS 8             // S-chunks for weighted sum
#define SCHUNK (S / SCHUNKS)  // 1024

// Scratch (static device globals; no allocation allowed)
__device__ float g_M[D * D];            // M = Wq @ Wk^T   (256 KB)
__device__ float g_vec[2 * D + 1];      // c1[256], c2[256], c0
__device__ float g_score[NTOK];         // raw scores       (512 KB)
__device__ float g_wpart[B * SCHUNKS * D2]; // partial weighted sums
// d_out layout: [output: B*2D][weights: B*S]

// ---------------------------------------------------------------------------
// Prep 1: M[i][j] = sum_k Wq[i][k] * Wk[j][k]
// ---------------------------------------------------------------------------
__global__ void prep_M(const float* __restrict__ wq, const float* __restrict__ wk) {
    __shared__ float aS[16][16];
    __shared__ float bS[16][17];
    int tx = threadIdx.x, ty = threadIdx.y;
    int i = blockIdx.y * 16 + ty;
    int j = blockIdx.x * 16 + tx;
    float acc = 0.f;
    for (int kt = 0; kt < D; kt += 16) {
        aS[ty][tx] = wq[(blockIdx.y * 16 + ty) * D + kt + tx];
        bS[ty][tx] = wk[(blockIdx.x * 16 + ty) * D + kt + tx];
        __syncthreads();
#pragma unroll
        for (int kk = 0; kk < 16; kk++)
            acc = fmaf(aS[ty][kk], bS[tx][kk], acc);
        __syncthreads();
    }
    g_M[i * D + j] = acc;
}

// ---------------------------------------------------------------------------
// Prep 2: c1[i] = Wq[i,:]·bk ; c2[i] = Wk[i,:]·bq ; c0 = bq·bk
// ---------------------------------------------------------------------------
__global__ void prep_vec(const float* __restrict__ wq, const float* __restrict__ bq,
                         const float* __restrict__ wk, const float* __restrict__ bk) {
    int i = threadIdx.x;
    float s1 = 0.f, s2 = 0.f;
    for (int k = 0; k < D; k++) {
        s1 = fmaf(wq[i * D + k], bk[k], s1);
        s2 = fmaf(wk[i * D + k], bq[k], s2);
    }
    g_vec[i] = s1;
    g_vec[D + i] = s2;
    if (i == 0) {
        float c0 = 0.f;
        for (int k = 0; k < D; k++) c0 = fmaf(bq[k], bk[k], c0);
        g_vec[2 * D] = c0;
    }
}

// ---------------------------------------------------------------------------
// Score: for each token, diag = vi·M·au^T + vi·c1 + au·c2 + c0, scaled.
// Block: 256 threads, 32 tokens. Threads: jg = lane (8 j-cols each),
// tg = warp (4 tokens each). acc[t][j] register tile, M & vi staged in smem.
// ---------------------------------------------------------------------------
__global__ __launch_bounds__(256) void score_kernel(const float* __restrict__ vi,
                                                    const float* __restrict__ au) {
    __shared__ float vi_s[TOK][32];
    __shared__ float m_s[32][D];
    __shared__ float c1_s[D];
    __shared__ float c2_s[D];

    const int tid = threadIdx.x;
    const int jg = tid & 31;   // lane: owns j = jg*8 .. jg*8+7
    const int tg = tid >> 5;   // warp: owns tokens tg*4 .. tg*4+3
    const int tok0 = blockIdx.x * TOK;

    c1_s[tid] = g_vec[tid];
    c2_s[tid] = g_vec[D + tid];

    float acc[4][8];
#pragma unroll
    for (int t = 0; t < 4; t++)
#pragma unroll
        for (int j = 0; j < 8; j++) acc[t][j] = 0.f;
    float bsum[4] = {0.f, 0.f, 0.f, 0.f};

    for (int ic = 0; ic < D; ic += 32) {
        // stage vi tile [32 tok x 32 dims] : 256 float4s, one per thread
        {
            int t = tid >> 3;
            int c = (tid & 7) * 4;
            float4 v = *(const float4*)(vi + (tok0 + t) * D + ic + c);
            *(float4*)&vi_s[t][c] = v;
        }
        // stage M tile [32 rows x 256 cols] : 2048 float4s, 8 per thread
        {
#pragma unroll
            for (int p = 0; p < 8; p++) {
                int idx = p * 256 + tid;      // float4 index, 0..2047
                int r = idx >> 6;             // row 0..31
                int c = (idx & 63) * 4;       // col 0..252
                *(float4*)&m_s[r][c] = *(const float4*)(g_M + (ic + r) * D + c);
            }
        }
        __syncthreads();
#pragma unroll
        for (int ii = 0; ii < 32; ii++) {
            const float4 m0 = *(const float4*)&m_s[ii][jg * 8];
            const float4 m1 = *(const float4*)&m_s[ii][jg * 8 + 4];
            const float c1v = c1_s[ic + ii];
#pragma unroll
            for (int t = 0; t < 4; t++) {
                const float v = vi_s[tg * 4 + t][ii];
                bsum[t] = fmaf(v, c1v, bsum[t]);
                acc[t][0] = fmaf(v, m0.x, acc[t][0]);
                acc[t][1] = fmaf(v, m0.y, acc[t][1]);
                acc[t][2] = fmaf(v, m0.z, acc[t][2]);
                acc[t][3] = fmaf(v, m0.w, acc[t][3]);
                acc[t][4] = fmaf(v, m1.x, acc[t][4]);
                acc[t][5] = fmaf(v, m1.y, acc[t][5]);
                acc[t][6] = fmaf(v, m1.z, acc[t][6]);
                acc[t][7] = fmaf(v, m1.w, acc[t][7]);
            }
        }
        __syncthreads();
    }

    // epilogue: dot with au, add bias terms, warp-reduce over j
    const float c0 = g_vec[2 * D];
#pragma unroll
    for (int t = 0; t < 4; t++) {
        const int tok = tok0 + tg * 4 + t;
        const float4 a0 = *(const float4*)(au + tok * D + jg * 8);
        const float4 a1 = *(const float4*)(au + tok * D + jg * 8 + 4);
        float p = 0.f;
        p = fmaf(acc[t][0] + c2_s[jg * 8 + 0], a0.x, p);
        p = fmaf(acc[t][1] + c2_s[jg * 8 + 1], a0.y, p);
        p = fmaf(acc[t][2] + c2_s[jg * 8 + 2], a0.z, p);
        p = fmaf(acc[t][3] + c2_s[jg * 8 + 3], a0.w, p);
        p = fmaf(acc[t][4] + c2_s[jg * 8 + 4], a1.x, p);
        p = fmaf(acc[t][5] + c2_s[jg * 8 + 5], a1.y, p);
        p = fmaf(acc[t][6] + c2_s[jg * 8 + 6], a1.z, p);
        p = fmaf(acc[t][7] + c2_s[jg * 8 + 7], a1.w, p);
#pragma unroll
        for (int o = 16; o > 0; o >>= 1) p += __shfl_down_sync(0xffffffffu, p, o);
        if (jg == 0) {
            g_score[tok] = (p + bsum[t] + c0) * 0.0625f;  // 1/sqrt(256)
        }
    }
}

// ---------------------------------------------------------------------------
// Softmax over S per batch; writes weights into d_out (after output section).
// ---------------------------------------------------------------------------
__global__ __launch_bounds__(1024) void softmax_kernel(float* __restrict__ out) {
    __shared__ float red[32];
    __shared__ float sh_val;
    const int b = blockIdx.x;
    const int tid = threadIdx.x;
    const int lane = tid & 31, warp = tid >> 5;
    const float* sc = g_score + b * S;
    float* w = out + B * D2 + b * S;

    float v[8];
    float mx = -CUDART_INF_F;
#pragma unroll
    for (int i = 0; i < 8; i++) {
        v[i] = sc[tid + i * 1024];
        mx = fmaxf(mx, v[i]);
    }
#pragma unroll
    for (int o = 16; o > 0; o >>= 1) mx = fmaxf(mx, __shfl_xor_sync(0xffffffffu, mx, o));
    if (lane == 0) red[warp] = mx;
    __syncthreads();
    if (warp == 0) {
        float m = red[lane];
#pragma unroll
        for (int o = 16; o > 0; o >>= 1) m = fmaxf(m, __shfl_xor_sync(0xffffffffu, m, o));
        if (lane == 0) sh_val = m;
    }
    __syncthreads();
    mx = sh_val;

    float sum = 0.f;
#pragma unroll
    for (int i = 0; i < 8; i++) {
        v[i] = expf(v[i] - mx);
        sum += v[i];
    }
#pragma unroll
    for (int o = 16; o > 0; o >>= 1) sum += __shfl_xor_sync(0xffffffffu, sum, o);
    if (lane == 0) red[warp] = sum;
    __syncthreads();
    if (warp == 0) {
        float s2 = red[lane];
#pragma unroll
        for (int o = 16; o > 0; o >>= 1) s2 += __shfl_xor_sync(0xffffffffu, s2, o);
        if (lane == 0) sh_val = s2;
    }
    __syncthreads();
    const float inv = 1.f / sh_val;
#pragma unroll
    for (int i = 0; i < 8; i++) w[tid + i * 1024] = v[i] * inv;
}

// ---------------------------------------------------------------------------
// Weighted sum of cat(vi, au): partial over S-chunks (deterministic, no atomics)
// ---------------------------------------------------------------------------
__global__ __launch_bounds__(512) void wsum_kernel(const float* __restrict__ vi,
                                                   const float* __restrict__ au,
                                                   const float* __restrict__ out) {
    const int chunk = blockIdx.x;
    const int b = blockIdx.y;
    const int e = threadIdx.x;  // 0..511
    const float* w = out + B * D2 + b * S + chunk * SCHUNK;
    const float* src = (e < D) ? (vi + ((long)b * S + chunk * SCHUNK) * D + e)
                               : (au + ((long)b * S + chunk * SCHUNK) * D + (e - D));
    float a0 = 0.f, a1 = 0.f, a2 = 0.f, a3 = 0.f;
#pragma unroll 1
    for (int s = 0; s < SCHUNK; s += 4) {
        a0 = fmaf(w[s + 0], src[(s + 0) * D], a0);
        a1 = fmaf(w[s + 1], src[(s + 1) * D], a1);
        a2 = fmaf(w[s + 2], src[(s + 2) * D], a2);
        a3 = fmaf(w[s + 3], src[(s + 3) * D], a3);
    }
    g_wpart[(b * SCHUNKS + chunk) * D2 + e] = (a0 + a1) + (a2 + a3);
}

// ---------------------------------------------------------------------------
// Final: wcat = sum of partials; output = wcat @ Wv + bv
// ---------------------------------------------------------------------------
__global__ __launch_bounds__(512) void out_kernel(const float* __restrict__ wv_w,
                                                  const float* __restrict__ wv_b,
                                                  float* __restrict__ out) {
    __shared__ float wc[D2];
    const int b = blockIdx.x;
    const int e = threadIdx.x;
    float a = 0.f;
#pragma unroll
    for (int c = 0; c < SCHUNKS; c++) a += g_wpart[(b * SCHUNKS + c) * D2 + e];
    wc[e] = a;
    __syncthreads();
    float o = wv_b[e];
#pragma unroll 4
    for (int f = 0; f < D2; f++) o = fmaf(wc[f], wv_w[f * D2 + e], o);
    out[b * D2 + e] = o;
}

// ---------------------------------------------------------------------------
extern "C" void kernel_launch(void* const* d_in, const int* in_sizes, int n_in,
                              void* d_out, int out_size) {
    const float* au   = (const float*)d_in[0];
    const float* vi   = (const float*)d_in[1];
    const float* wq_w = (const float*)d_in[2];
    const float* wq_b = (const float*)d_in[3];
    const float* wk_w = (const float*)d_in[4];
    const float* wk_b = (const float*)d_in[5];
    const float* wv_w = (const float*)d_in[6];
    const float* wv_b = (const float*)d_in[7];
    float* out = (float*)d_out;

    prep_M<<<dim3(16, 16), dim3(16, 16)>>>(wq_w, wk_w);
    prep_vec<<<1, 256>>>(wq_w, wq_b, wk_w, wk_b);
    score_kernel<<<NTOK / TOK, 256>>>(vi, au);
    softmax_kernel<<<B, 1024>>>(out);
    wsum_kernel<<<dim3(SCHUNKS, B), D2>>>(vi, au, out);
    out_kernel<<<B, D2>>>(wv_w, wv_b, out);
}

// round 5
// speedup vs baseline: 1.5429x; 1.5429x over previous
#include <cuda_runtime.h>
#include <cuda_bf16.h>
#include <math_constants.h>
#include <cstdint>

// Problem constants
#define B 16
#define S 8192
#define D 256
#define D2 512
#define NTOK (B * S)          // 131072 tokens
#define MTILE 128             // tokens per score CTA
#define SCHUNKS 8
#define SCHUNK (S / SCHUNKS)  // 1024

// ---------------------------------------------------------------------------
// Device scratch
// ---------------------------------------------------------------------------
// B operand = M^T as bf16 hi/lo, n-major (row n holds k=0..255 contiguous)
__device__ __align__(16) __nv_bfloat16 g_Bhi[D * D];
__device__ __align__(16) __nv_bfloat16 g_Blo[D * D];
__device__ float g_vec[2 * D + 1];      // c1[256], c2[256], c0
__device__ float g_score[NTOK];
__device__ float g_wpart[B * SCHUNKS * D2];
// d_out layout: [output: B*2D][weights: B*S]

// ---------------------------------------------------------------------------
// Helpers
// ---------------------------------------------------------------------------
__device__ __forceinline__ uint32_t smem_u32(const void* p) {
    uint32_t a;
    asm("{ .reg .u64 t; cvta.to.shared.u64 t, %1; cvt.u32.u64 %0, t; }"
        : "=r"(a) : "l"(p));
    return a;
}
__device__ __forceinline__ void ldsm_x4(uint32_t* r, uint32_t addr) {
    asm volatile("ldmatrix.sync.aligned.m8n8.x4.shared.b16 {%0,%1,%2,%3}, [%4];"
                 : "=r"(r[0]), "=r"(r[1]), "=r"(r[2]), "=r"(r[3]) : "r"(addr));
}
__device__ __forceinline__ void ldsm_x2(uint32_t& r0, uint32_t& r1, uint32_t addr) {
    asm volatile("ldmatrix.sync.aligned.m8n8.x2.shared.b16 {%0,%1}, [%2];"
                 : "=r"(r0), "=r"(r1) : "r"(addr));
}
__device__ __forceinline__ void mma16816(float* d, const uint32_t* a,
                                         uint32_t b0, uint32_t b1) {
    asm volatile(
        "mma.sync.aligned.m16n8k16.row.col.f32.bf16.bf16.f32 "
        "{%0,%1,%2,%3}, {%4,%5,%6,%7}, {%8,%9}, {%0,%1,%2,%3};"
        : "+f"(d[0]), "+f"(d[1]), "+f"(d[2]), "+f"(d[3])
        : "r"(a[0]), "r"(a[1]), "r"(a[2]), "r"(a[3]), "r"(b0), "r"(b1));
}

// ---------------------------------------------------------------------------
// Prep 1: Bmat[n][k] = M[k][n] = Wq[k,:]·Wk[n,:]  -> bf16 hi/lo, n-major
// ---------------------------------------------------------------------------
__global__ void prep_M(const float* __restrict__ wq, const float* __restrict__ wk) {
    __shared__ float aS[16][16];
    __shared__ float bS[16][17];
    int tx = threadIdx.x, ty = threadIdx.y;
    int i = blockIdx.y * 16 + ty;   // k index
    int j = blockIdx.x * 16 + tx;   // n index
    float acc = 0.f;
    for (int kt = 0; kt < D; kt += 16) {
        aS[ty][tx] = wq[(blockIdx.y * 16 + ty) * D + kt + tx];
        bS[ty][tx] = wk[(blockIdx.x * 16 + ty) * D + kt + tx];
        __syncthreads();
#pragma unroll
        for (int kk = 0; kk < 16; kk++)
            acc = fmaf(aS[ty][kk], bS[tx][kk], acc);
        __syncthreads();
    }
    __nv_bfloat16 hi = __float2bfloat16(acc);
    __nv_bfloat16 lo = __float2bfloat16(acc - __bfloat162float(hi));
    g_Bhi[j * D + i] = hi;
    g_Blo[j * D + i] = lo;
}

// ---------------------------------------------------------------------------
// Prep 2: c1[i] = Wq[i,:]·bk ; c2[i] = Wk[i,:]·bq ; c0 = bq·bk
// ---------------------------------------------------------------------------
__global__ void prep_vec(const float* __restrict__ wq, const float* __restrict__ bq,
                         const float* __restrict__ wk, const float* __restrict__ bk) {
    int i = threadIdx.x;
    float s1 = 0.f, s2 = 0.f;
    for (int k = 0; k < D; k++) {
        s1 = fmaf(wq[i * D + k], bk[k], s1);
        s2 = fmaf(wk[i * D + k], bq[k], s2);
    }
    g_vec[i] = s1;
    g_vec[D + i] = s2;
    if (i == 0) {
        float c0 = 0.f;
        for (int k = 0; k < D; k++) c0 = fmaf(bq[k], bk[k], c0);
        g_vec[2 * D] = c0;
    }
}

// ---------------------------------------------------------------------------
// Score kernel (mma.sync bf16 split): 128 tokens / CTA, 8 warps.
// Warp (w%4, w/4): m-rows 32*(w%4)..+31 (two m16 tiles), n-half 128*(w/4).
// Dyn smem: A_hi [128 x 528B]  A_lo [128 x 528B]  B_hi [256 x 144B]  B_lo [...]
// ---------------------------------------------------------------------------
#define A_PITCH 528
#define B_PITCH 144
#define SM_AHI 0
#define SM_ALO (128 * A_PITCH)            // 67584
#define SM_BHI (2 * 128 * A_PITCH)        // 135168
#define SM_BLO (SM_BHI + 256 * B_PITCH)   // 172032
#define DSMEM_BYTES (SM_BLO + 256 * B_PITCH)  // 208896

__global__ __launch_bounds__(256, 1) void score_kernel(const float* __restrict__ vi,
                                                       const float* __restrict__ au) {
    extern __shared__ __align__(16) char dsm[];
    __shared__ float c1_s[D];
    __shared__ float c2_s[D];
    __shared__ float bpart[256];
    __shared__ float spart[2][128];

    const int tid = threadIdx.x;
    const int lane = tid & 31;
    const int w = tid >> 5;
    const int mbase = (w & 3) * 32;
    const int nhalf = w >> 2;
    const int tok0 = blockIdx.x * MTILE;
    const uint32_t sbase = smem_u32(dsm);

    c1_s[tid] = g_vec[tid];
    c2_s[tid] = g_vec[D + tid];
    __syncthreads();

    // ---- Convert vi tile to bf16 hi/lo in smem; fold vi·c1 into bpart
    {
        const int r = tid >> 1;
        const int kb = (tid & 1) * 128;
        const float* vrow = vi + (size_t)(tok0 + r) * D + kb;
        char* dhi = dsm + SM_AHI + r * A_PITCH + kb * 2;
        char* dlo = dsm + SM_ALO + r * A_PITCH + kb * 2;
        float bs = 0.f;
#pragma unroll 4
        for (int k8 = 0; k8 < 128; k8 += 8) {
            float4 v0 = *(const float4*)(vrow + k8);
            float4 v1 = *(const float4*)(vrow + k8 + 4);
            float vv[8] = {v0.x, v0.y, v0.z, v0.w, v1.x, v1.y, v1.z, v1.w};
            uint32_t hw[4], lw[4];
#pragma unroll
            for (int u = 0; u < 4; u++) {
                float a = vv[2 * u], bvl = vv[2 * u + 1];
                bs = fmaf(a, c1_s[kb + k8 + 2 * u], bs);
                bs = fmaf(bvl, c1_s[kb + k8 + 2 * u + 1], bs);
                __nv_bfloat16 ha = __float2bfloat16(a);
                __nv_bfloat16 hb = __float2bfloat16(bvl);
                __nv_bfloat162 hp; hp.x = ha; hp.y = hb;
                hw[u] = *(uint32_t*)&hp;
                __nv_bfloat16 la = __float2bfloat16(a - __bfloat162float(ha));
                __nv_bfloat16 lb = __float2bfloat16(bvl - __bfloat162float(hb));
                __nv_bfloat162 lp; lp.x = la; lp.y = lb;
                lw[u] = *(uint32_t*)&lp;
            }
            *(uint4*)(dhi + k8 * 2) = make_uint4(hw[0], hw[1], hw[2], hw[3]);
            *(uint4*)(dlo + k8 * 2) = make_uint4(lw[0], lw[1], lw[2], lw[3]);
        }
        bpart[tid] = bs;
    }

    // ---- ldmatrix lane addressing
    const uint32_t a_lane = (uint32_t)((lane & 15) * A_PITCH + ((lane >> 4) << 4));
    const uint32_t aH = sbase + SM_AHI + mbase * A_PITCH + a_lane;
    const uint32_t aL = sbase + SM_ALO + mbase * A_PITCH + a_lane;
    const uint32_t b_lane = (uint32_t)((lane & 7) * B_PITCH + ((lane & 8) ? 16 : 0));
    const uint32_t bH = sbase + SM_BHI + nhalf * 128 * B_PITCH + b_lane;
    const uint32_t bL = sbase + SM_BLO + nhalf * 128 * B_PITCH + b_lane;

    float acc[2][16][4] = {};

#pragma unroll 1
    for (int c = 0; c < 4; c++) {
        __syncthreads();   // prev chunk consumed (1st iter: A conversion visible)
        {   // stage B chunk: 256 n-rows x 64 k (128B) -> 144B pitch rows
            const uint4* srcH = (const uint4*)(g_Bhi + tid * D + c * 64);
            const uint4* srcL = (const uint4*)(g_Blo + tid * D + c * 64);
            uint4* dH = (uint4*)(dsm + SM_BHI + tid * B_PITCH);
            uint4* dL = (uint4*)(dsm + SM_BLO + tid * B_PITCH);
#pragma unroll
            for (int q = 0; q < 8; q++) { dH[q] = srcH[q]; dL[q] = srcL[q]; }
        }
        __syncthreads();

#pragma unroll
        for (int ks = 0; ks < 4; ks++) {
            const uint32_t k2 = (uint32_t)((c * 64 + ks * 16) * 2);
            uint32_t ah[2][4], al[2][4];
            ldsm_x4(ah[0], aH + k2);
            ldsm_x4(ah[1], aH + 16 * A_PITCH + k2);
            ldsm_x4(al[0], aL + k2);
            ldsm_x4(al[1], aL + 16 * A_PITCH + k2);
#pragma unroll
            for (int nt = 0; nt < 16; nt++) {
                const uint32_t bo = (uint32_t)(nt * 8 * B_PITCH + ks * 32);
                uint32_t bh0, bh1, bl0, bl1;
                ldsm_x2(bh0, bh1, bH + bo);
                ldsm_x2(bl0, bl1, bL + bo);
#pragma unroll
                for (int mt = 0; mt < 2; mt++) {
                    mma16816(acc[mt][nt], ah[mt], bh0, bh1);
                    mma16816(acc[mt][nt], ah[mt], bl0, bl1);
                    mma16816(acc[mt][nt], al[mt], bh0, bh1);
                }
            }
        }
    }

    // ---- Epilogue: part[t] = sum_n (Q'[t][n]+c2[n]) * au[t][n]
    float prow[2][2] = {};
#pragma unroll
    for (int mt = 0; mt < 2; mt++) {
        const float* au0 = au + (size_t)(tok0 + mbase + mt * 16 + (lane >> 2)) * D;
        const float* au1 = au0 + 8 * D;
#pragma unroll
        for (int nt = 0; nt < 16; nt++) {
            const int n = nhalf * 128 + nt * 8 + (lane & 3) * 2;
            const float2 c2v = *(const float2*)&c2_s[n];
            const float2 x0 = __ldg((const float2*)(au0 + n));
            const float2 x1 = __ldg((const float2*)(au1 + n));
            prow[mt][0] = fmaf(acc[mt][nt][0] + c2v.x, x0.x, prow[mt][0]);
            prow[mt][0] = fmaf(acc[mt][nt][1] + c2v.y, x0.y, prow[mt][0]);
            prow[mt][1] = fmaf(acc[mt][nt][2] + c2v.x, x1.x, prow[mt][1]);
            prow[mt][1] = fmaf(acc[mt][nt][3] + c2v.y, x1.y, prow[mt][1]);
        }
    }
#pragma unroll
    for (int mt = 0; mt < 2; mt++)
#pragma unroll
        for (int j = 0; j < 2; j++) {
            float v = prow[mt][j];
            v += __shfl_xor_sync(0xffffffffu, v, 1);
            v += __shfl_xor_sync(0xffffffffu, v, 2);
            if ((lane & 3) == 0)
                spart[nhalf][mbase + mt * 16 + j * 8 + (lane >> 2)] = v;
        }
    __syncthreads();

    if (tid < 128) {
        const float c0 = g_vec[2 * D];
        float s = spart[0][tid] + spart[1][tid] + bpart[2 * tid] + bpart[2 * tid + 1] + c0;
        g_score[tok0 + tid] = s * 0.0625f;   // 1/sqrt(256)
    }
}

// ---------------------------------------------------------------------------
// Softmax over S per batch; writes weights into d_out (after output section).
// ---------------------------------------------------------------------------
__global__ __launch_bounds__(1024) void softmax_kernel(float* __restrict__ out) {
    __shared__ float red[32];
    __shared__ float sh_val;
    const int b = blockIdx.x;
    const int tid = threadIdx.x;
    const int lane = tid & 31, warp = tid >> 5;
    const float* sc = g_score + b * S;
    float* w = out + B * D2 + b * S;

    float v[8];
    float mx = -CUDART_INF_F;
#pragma unroll
    for (int i = 0; i < 8; i++) {
        v[i] = sc[tid + i * 1024];
        mx = fmaxf(mx, v[i]);
    }
#pragma unroll
    for (int o = 16; o > 0; o >>= 1) mx = fmaxf(mx, __shfl_xor_sync(0xffffffffu, mx, o));
    if (lane == 0) red[warp] = mx;
    __syncthreads();
    if (warp == 0) {
        float m = red[lane];
#pragma unroll
        for (int o = 16; o > 0; o >>= 1) m = fmaxf(m, __shfl_xor_sync(0xffffffffu, m, o));
        if (lane == 0) sh_val = m;
    }
    __syncthreads();
    mx = sh_val;

    float sum = 0.f;
#pragma unroll
    for (int i = 0; i < 8; i++) {
        v[i] = expf(v[i] - mx);
        sum += v[i];
    }
#pragma unroll
    for (int o = 16; o > 0; o >>= 1) sum += __shfl_xor_sync(0xffffffffu, sum, o);
    if (lane == 0) red[warp] = sum;
    __syncthreads();
    if (warp == 0) {
        float s2 = red[lane];
#pragma unroll
        for (int o = 16; o > 0; o >>= 1) s2 += __shfl_xor_sync(0xffffffffu, s2, o);
        if (lane == 0) sh_val = s2;
    }
    __syncthreads();
    const float inv = 1.f / sh_val;
#pragma unroll
    for (int i = 0; i < 8; i++) w[tid + i * 1024] = v[i] * inv;
}

// ---------------------------------------------------------------------------
// Weighted sum of cat(vi, au): partial over S-chunks
// ---------------------------------------------------------------------------
__global__ __launch_bounds__(512) void wsum_kernel(const float* __restrict__ vi,
                                                   const float* __restrict__ au,
                                                   const float* __restrict__ out) {
    const int chunk = blockIdx.x;
    const int b = blockIdx.y;
    const int e = threadIdx.x;  // 0..511
    const float* w = out + B * D2 + b * S + chunk * SCHUNK;
    const float* src = (e < D) ? (vi + ((long)b * S + chunk * SCHUNK) * D + e)
                               : (au + ((long)b * S + chunk * SCHUNK) * D + (e - D));
    float a0 = 0.f, a1 = 0.f, a2 = 0.f, a3 = 0.f;
    float a4 = 0.f, a5 = 0.f, a6 = 0.f, a7 = 0.f;
#pragma unroll 1
    for (int s = 0; s < SCHUNK; s += 8) {
        a0 = fmaf(w[s + 0], src[(s + 0) * D], a0);
        a1 = fmaf(w[s + 1], src[(s + 1) * D], a1);
        a2 = fmaf(w[s + 2], src[(s + 2) * D], a2);
        a3 = fmaf(w[s + 3], src[(s + 3) * D], a3);
        a4 = fmaf(w[s + 4], src[(s + 4) * D], a4);
        a5 = fmaf(w[s + 5], src[(s + 5) * D], a5);
        a6 = fmaf(w[s + 6], src[(s + 6) * D], a6);
        a7 = fmaf(w[s + 7], src[(s + 7) * D], a7);
    }
    g_wpart[(b * SCHUNKS + chunk) * D2 + e] =
        ((a0 + a1) + (a2 + a3)) + ((a4 + a5) + (a6 + a7));
}

// ---------------------------------------------------------------------------
// Final: wcat = sum of partials; output = wcat @ Wv + bv
// ---------------------------------------------------------------------------
__global__ __launch_bounds__(512) void out_kernel(const float* __restrict__ wv_w,
                                                  const float* __restrict__ wv_b,
                                                  float* __restrict__ out) {
    __shared__ float wc[D2];
    const int b = blockIdx.x;
    const int e = threadIdx.x;
    float a = 0.f;
#pragma unroll
    for (int c = 0; c < SCHUNKS; c++) a += g_wpart[(b * SCHUNKS + c) * D2 + e];
    wc[e] = a;
    __syncthreads();
    float o = wv_b[e];
#pragma unroll 4
    for (int f = 0; f < D2; f++) o = fmaf(wc[f], wv_w[f * D2 + e], o);
    out[b * D2 + e] = o;
}

// ---------------------------------------------------------------------------
extern "C" void kernel_launch(void* const* d_in, const int* in_sizes, int n_in,
                              void* d_out, int out_size) {
    const float* au   = (const float*)d_in[0];
    const float* vi   = (const float*)d_in[1];
    const float* wq_w = (const float*)d_in[2];
    const float* wq_b = (const float*)d_in[3];
    const float* wk_w = (const float*)d_in[4];
    const float* wk_b = (const float*)d_in[5];
    const float* wv_w = (const float*)d_in[6];
    const float* wv_b = (const float*)d_in[7];
    float* out = (float*)d_out;

    static int smem_set = 0;
    if (!smem_set) {
        cudaFuncSetAttribute(score_kernel, cudaFuncAttributeMaxDynamicSharedMemorySize,
                             DSMEM_BYTES);
        smem_set = 1;
    }

    prep_M<<<dim3(16, 16), dim3(16, 16)>>>(wq_w, wk_w);
    prep_vec<<<1, 256>>>(wq_w, wq_b, wk_w, wk_b);
    score_kernel<<<NTOK / MTILE, 256, DSMEM_BYTES>>>(vi, au);
    softmax_kernel<<<B, 1024>>>(out);
    wsum_kernel<<<dim3(SCHUNKS, B), D2>>>(vi, au, out);
    out_kernel<<<B, D2>>>(wv_w, wv_b, out);
}

// round 6
// speedup vs baseline: 1.6319x; 1.0577x over previous
#include <cuda_runtime.h>
#include <cuda_bf16.h>
#include <math_constants.h>
#include <cstdint>

// Problem constants
#define B 16
#define S 8192
#define D 256
#define D2 512
#define NTOK (B * S)          // 131072 tokens
#define MTILE 128             // tokens per score CTA
#define SCHUNKS 8
#define SCHUNK (S / SCHUNKS)  // 1024

// ---------------------------------------------------------------------------
// Device scratch
// ---------------------------------------------------------------------------
// B operand = M^T as bf16 hi/lo, n-major (row n holds k=0..255 contiguous)
__device__ __align__(16) __nv_bfloat16 g_Bhi[D * D];
__device__ __align__(16) __nv_bfloat16 g_Blo[D * D];
__device__ float g_vec[2 * D + 1];      // c1[256], c2[256], c0
__device__ float g_score[NTOK];
__device__ float g_wpart[B * SCHUNKS * D2];
// d_out layout: [output: B*2D][weights: B*S]

// ---------------------------------------------------------------------------
// Helpers
// ---------------------------------------------------------------------------
__device__ __forceinline__ uint32_t smem_u32(const void* p) {
    uint32_t a;
    asm("{ .reg .u64 t; cvta.to.shared.u64 t, %1; cvt.u32.u64 %0, t; }"
        : "=r"(a) : "l"(p));
    return a;
}
__device__ __forceinline__ void ldsm_x4(uint32_t* r, uint32_t addr) {
    asm volatile("ldmatrix.sync.aligned.m8n8.x4.shared.b16 {%0,%1,%2,%3}, [%4];"
                 : "=r"(r[0]), "=r"(r[1]), "=r"(r[2]), "=r"(r[3]) : "r"(addr));
}
__device__ __forceinline__ void mma16816(float* d, const uint32_t* a,
                                         uint32_t b0, uint32_t b1) {
    asm volatile(
        "mma.sync.aligned.m16n8k16.row.col.f32.bf16.bf16.f32 "
        "{%0,%1,%2,%3}, {%4,%5,%6,%7}, {%8,%9}, {%0,%1,%2,%3};"
        : "+f"(d[0]), "+f"(d[1]), "+f"(d[2]), "+f"(d[3])
        : "r"(a[0]), "r"(a[1]), "r"(a[2]), "r"(a[3]), "r"(b0), "r"(b1));
}

// ---------------------------------------------------------------------------
// Prep 1: Bmat[n][k] = M[k][n] = Wq[k,:]·Wk[n,:]  -> bf16 hi/lo, n-major
// ---------------------------------------------------------------------------
__global__ void prep_M(const float* __restrict__ wq, const float* __restrict__ wk) {
    __shared__ float aS[16][16];
    __shared__ float bS[16][17];
    int tx = threadIdx.x, ty = threadIdx.y;
    int i = blockIdx.y * 16 + ty;   // k index
    int j = blockIdx.x * 16 + tx;   // n index
    float acc = 0.f;
    for (int kt = 0; kt < D; kt += 16) {
        aS[ty][tx] = wq[(blockIdx.y * 16 + ty) * D + kt + tx];
        bS[ty][tx] = wk[(blockIdx.x * 16 + ty) * D + kt + tx];
        __syncthreads();
#pragma unroll
        for (int kk = 0; kk < 16; kk++)
            acc = fmaf(aS[ty][kk], bS[tx][kk], acc);
        __syncthreads();
    }
    __nv_bfloat16 hi = __float2bfloat16(acc);
    __nv_bfloat16 lo = __float2bfloat16(acc - __bfloat162float(hi));
    g_Bhi[j * D + i] = hi;
    g_Blo[j * D + i] = lo;
}

// ---------------------------------------------------------------------------
// Prep 2: c1[i] = Wq[i,:]·bk ; c2[i] = Wk[i,:]·bq ; c0 = bq·bk
// ---------------------------------------------------------------------------
__global__ void prep_vec(const float* __restrict__ wq, const float* __restrict__ bq,
                         const float* __restrict__ wk, const float* __restrict__ bk) {
    int i = threadIdx.x;
    float s1 = 0.f, s2 = 0.f;
    for (int k = 0; k < D; k++) {
        s1 = fmaf(wq[i * D + k], bk[k], s1);
        s2 = fmaf(wk[i * D + k], bq[k], s2);
    }
    g_vec[i] = s1;
    g_vec[D + i] = s2;
    if (i == 0) {
        float c0 = 0.f;
        for (int k = 0; k < D; k++) c0 = fmaf(bq[k], bk[k], c0);
        g_vec[2 * D] = c0;
    }
}

// ---------------------------------------------------------------------------
// Score kernel (mma.sync bf16 split): 128 tokens / CTA, 16 warps (4m x 4n).
// Warp (w&3, w>>2): m-rows 32*(w&3)..+31 (two m16 tiles), n-quarter 64*(w>>2).
// Dyn smem: A_hi [128 x 528B]  A_lo [128 x 528B]  B_hi [256 x 144B]  B_lo [...]
// ---------------------------------------------------------------------------
#define A_PITCH 528
#define B_PITCH 144
#define SM_AHI 0
#define SM_ALO (128 * A_PITCH)            // 67584
#define SM_BHI (2 * 128 * A_PITCH)        // 135168
#define SM_BLO (SM_BHI + 256 * B_PITCH)   // 172032
#define DSMEM_BYTES (SM_BLO + 256 * B_PITCH)  // 208896

__global__ __launch_bounds__(512, 1) void score_kernel(const float* __restrict__ vi,
                                                       const float* __restrict__ au) {
    extern __shared__ __align__(16) char dsm[];
    __shared__ float c1_s[D];
    __shared__ float c2_s[D];
    __shared__ float bpart[512];
    __shared__ float spart[4][128];

    const int tid = threadIdx.x;
    const int lane = tid & 31;
    const int w = tid >> 5;
    const int mbase = (w & 3) * 32;
    const int nq = w >> 2;                 // n-quarter 0..3
    const int tok0 = blockIdx.x * MTILE;
    const uint32_t sbase = smem_u32(dsm);

    if (tid < 256) {
        c1_s[tid] = g_vec[tid];
        c2_s[tid] = g_vec[D + tid];
    }
    __syncthreads();

    // ---- Convert vi tile to bf16 hi/lo in smem; fold vi·c1 into bpart
    {
        const int r = tid >> 2;            // token row 0..127
        const int kb = (tid & 3) * 64;     // k-range start
        const float* vrow = vi + (size_t)(tok0 + r) * D + kb;
        char* dhi = dsm + SM_AHI + r * A_PITCH + kb * 2;
        char* dlo = dsm + SM_ALO + r * A_PITCH + kb * 2;
        float bs = 0.f;
#pragma unroll 2
        for (int k8 = 0; k8 < 64; k8 += 8) {
            float4 v0 = *(const float4*)(vrow + k8);
            float4 v1 = *(const float4*)(vrow + k8 + 4);
            float vv[8] = {v0.x, v0.y, v0.z, v0.w, v1.x, v1.y, v1.z, v1.w};
            uint32_t hw[4], lw[4];
#pragma unroll
            for (int u = 0; u < 4; u++) {
                float a = vv[2 * u], bvl = vv[2 * u + 1];
                bs = fmaf(a, c1_s[kb + k8 + 2 * u], bs);
                bs = fmaf(bvl, c1_s[kb + k8 + 2 * u + 1], bs);
                __nv_bfloat16 ha = __float2bfloat16(a);
                __nv_bfloat16 hb = __float2bfloat16(bvl);
                __nv_bfloat162 hp; hp.x = ha; hp.y = hb;
                hw[u] = *(uint32_t*)&hp;
                __nv_bfloat16 la = __float2bfloat16(a - __bfloat162float(ha));
                __nv_bfloat16 lb = __float2bfloat16(bvl - __bfloat162float(hb));
                __nv_bfloat162 lp; lp.x = la; lp.y = lb;
                lw[u] = *(uint32_t*)&lp;
            }
            *(uint4*)(dhi + k8 * 2) = make_uint4(hw[0], hw[1], hw[2], hw[3]);
            *(uint4*)(dlo + k8 * 2) = make_uint4(lw[0], lw[1], lw[2], lw[3]);
        }
        bpart[tid] = bs;
    }

    // ---- ldmatrix lane addressing
    const uint32_t a_lane = (uint32_t)((lane & 15) * A_PITCH + ((lane >> 4) << 4));
    const uint32_t aH = sbase + SM_AHI + mbase * A_PITCH + a_lane;
    const uint32_t aL = sbase + SM_ALO + mbase * A_PITCH + a_lane;
    // B x4: m0=(n0-7,k0-7) m1=(n0-7,k8-15) m2=(n8-15,k0-7) m3=(n8-15,k8-15)
    const uint32_t b_lane =
        (uint32_t)(((lane & 7) + ((lane >> 4) << 3)) * B_PITCH + ((lane & 8) ? 16 : 0));
    const uint32_t bH = sbase + SM_BHI + nq * 64 * B_PITCH + b_lane;
    const uint32_t bL = sbase + SM_BLO + nq * 64 * B_PITCH + b_lane;

    float acc[2][8][4] = {};

#pragma unroll 1
    for (int c = 0; c < 4; c++) {
        __syncthreads();   // prev chunk consumed (1st iter: A conversion visible)
        {   // stage B chunk: 256 n-rows x 64 k (128B) -> 144B pitch rows
            const int row = tid >> 1;
            const int half = tid & 1;
            const uint4* srcH = (const uint4*)(g_Bhi + row * D + c * 64 + half * 32);
            const uint4* srcL = (const uint4*)(g_Blo + row * D + c * 64 + half * 32);
            uint4* dH = (uint4*)(dsm + SM_BHI + row * B_PITCH + half * 64);
            uint4* dL = (uint4*)(dsm + SM_BLO + row * B_PITCH + half * 64);
#pragma unroll
            for (int q = 0; q < 4; q++) { dH[q] = srcH[q]; dL[q] = srcL[q]; }
        }
        __syncthreads();

#pragma unroll
        for (int ks = 0; ks < 4; ks++) {
            const uint32_t ka = (uint32_t)((c * 64 + ks * 16) * 2);  // A byte off
            const uint32_t kb2 = (uint32_t)(ks * 32);                // B byte off
            uint32_t ah[2][4], al[2][4];
            ldsm_x4(ah[0], aH + ka);
            ldsm_x4(ah[1], aH + 16 * A_PITCH + ka);
            ldsm_x4(al[0], aL + ka);
            ldsm_x4(al[1], aL + 16 * A_PITCH + ka);
#pragma unroll
            for (int nt2 = 0; nt2 < 4; nt2++) {
                const uint32_t bo = (uint32_t)(nt2 * 16 * B_PITCH) + kb2;
                uint32_t bh4[4], bl4[4];
                ldsm_x4(bh4, bH + bo);
                ldsm_x4(bl4, bL + bo);
#pragma unroll
                for (int sub = 0; sub < 2; sub++) {
                    const int nt = nt2 * 2 + sub;
                    const uint32_t b0h = bh4[2 * sub], b1h = bh4[2 * sub + 1];
                    const uint32_t b0l = bl4[2 * sub], b1l = bl4[2 * sub + 1];
#pragma unroll
                    for (int mt = 0; mt < 2; mt++) {
                        mma16816(acc[mt][nt], ah[mt], b0h, b1h);
                        mma16816(acc[mt][nt], ah[mt], b0l, b1l);
                        mma16816(acc[mt][nt], al[mt], b0h, b1h);
                    }
                }
            }
        }
    }

    // ---- Epilogue: part[t] = sum_n (Q'[t][n]+c2[n]) * au[t][n]
    float prow[2][2] = {};
#pragma unroll
    for (int mt = 0; mt < 2; mt++) {
        const float* au0 = au + (size_t)(tok0 + mbase + mt * 16 + (lane >> 2)) * D;
        const float* au1 = au0 + 8 * D;
#pragma unroll
        for (int nt = 0; nt < 8; nt++) {
            const int n = nq * 64 + nt * 8 + (lane & 3) * 2;
            const float2 c2v = *(const float2*)&c2_s[n];
            const float2 x0 = __ldg((const float2*)(au0 + n));
            const float2 x1 = __ldg((const float2*)(au1 + n));
            prow[mt][0] = fmaf(acc[mt][nt][0] + c2v.x, x0.x, prow[mt][0]);
            prow[mt][0] = fmaf(acc[mt][nt][1] + c2v.y, x0.y, prow[mt][0]);
            prow[mt][1] = fmaf(acc[mt][nt][2] + c2v.x, x1.x, prow[mt][1]);
            prow[mt][1] = fmaf(acc[mt][nt][3] + c2v.y, x1.y, prow[mt][1]);
        }
    }
#pragma unroll
    for (int mt = 0; mt < 2; mt++)
#pragma unroll
        for (int j = 0; j < 2; j++) {
            float v = prow[mt][j];
            v += __shfl_xor_sync(0xffffffffu, v, 1);
            v += __shfl_xor_sync(0xffffffffu, v, 2);
            if ((lane & 3) == 0)
                spart[nq][mbase + mt * 16 + j * 8 + (lane >> 2)] = v;
        }
    __syncthreads();

    if (tid < 128) {
        const float c0 = g_vec[2 * D];
        float s = spart[0][tid] + spart[1][tid] + spart[2][tid] + spart[3][tid]
                + ((bpart[4 * tid] + bpart[4 * tid + 1])
                   + (bpart[4 * tid + 2] + bpart[4 * tid + 3]))
                + c0;
        g_score[tok0 + tid] = s * 0.0625f;   // 1/sqrt(256)
    }
}

// ---------------------------------------------------------------------------
// Softmax over S per batch; writes weights into d_out (after output section).
// ---------------------------------------------------------------------------
__global__ __launch_bounds__(1024) void softmax_kernel(float* __restrict__ out) {
    __shared__ float red[32];
    __shared__ float sh_val;
    const int b = blockIdx.x;
    const int tid = threadIdx.x;
    const int lane = tid & 31, warp = tid >> 5;
    const float* sc = g_score + b * S;
    float* w = out + B * D2 + b * S;

    float v[8];
    float mx = -CUDART_INF_F;
#pragma unroll
    for (int i = 0; i < 8; i++) {
        v[i] = sc[tid + i * 1024];
        mx = fmaxf(mx, v[i]);
    }
#pragma unroll
    for (int o = 16; o > 0; o >>= 1) mx = fmaxf(mx, __shfl_xor_sync(0xffffffffu, mx, o));
    if (lane == 0) red[warp] = mx;
    __syncthreads();
    if (warp == 0) {
        float m = red[lane];
#pragma unroll
        for (int o = 16; o > 0; o >>= 1) m = fmaxf(m, __shfl_xor_sync(0xffffffffu, m, o));
        if (lane == 0) sh_val = m;
    }
    __syncthreads();
    mx = sh_val;

    float sum = 0.f;
#pragma unroll
    for (int i = 0; i < 8; i++) {
        v[i] = expf(v[i] - mx);
        sum += v[i];
    }
#pragma unroll
    for (int o = 16; o > 0; o >>= 1) sum += __shfl_xor_sync(0xffffffffu, sum, o);
    if (lane == 0) red[warp] = sum;
    __syncthreads();
    if (warp == 0) {
        float s2 = red[lane];
#pragma unroll
        for (int o = 16; o > 0; o >>= 1) s2 += __shfl_xor_sync(0xffffffffu, s2, o);
        if (lane == 0) sh_val = s2;
    }
    __syncthreads();
    const float inv = 1.f / sh_val;
#pragma unroll
    for (int i = 0; i < 8; i++) w[tid + i * 1024] = v[i] * inv;
}

// ---------------------------------------------------------------------------
// Weighted sum of cat(vi, au): partial over S-chunks
// ---------------------------------------------------------------------------
__global__ __launch_bounds__(512) void wsum_kernel(const float* __restrict__ vi,
                                                   const float* __restrict__ au,
                                                   const float* __restrict__ out) {
    const int chunk = blockIdx.x;
    const int b = blockIdx.y;
    const int e = threadIdx.x;  // 0..511
    const float* w = out + B * D2 + b * S + chunk * SCHUNK;
    const float* src = (e < D) ? (vi + ((long)b * S + chunk * SCHUNK) * D + e)
                               : (au + ((long)b * S + chunk * SCHUNK) * D + (e - D));
    float a0 = 0.f, a1 = 0.f, a2 = 0.f, a3 = 0.f;
    float a4 = 0.f, a5 = 0.f, a6 = 0.f, a7 = 0.f;
#pragma unroll 1
    for (int s = 0; s < SCHUNK; s += 8) {
        a0 = fmaf(w[s + 0], src[(s + 0) * D], a0);
        a1 = fmaf(w[s + 1], src[(s + 1) * D], a1);
        a2 = fmaf(w[s + 2], src[(s + 2) * D], a2);
        a3 = fmaf(w[s + 3], src[(s + 3) * D], a3);
        a4 = fmaf(w[s + 4], src[(s + 4) * D], a4);
        a5 = fmaf(w[s + 5], src[(s + 5) * D], a5);
        a6 = fmaf(w[s + 6], src[(s + 6) * D], a6);
        a7 = fmaf(w[s + 7], src[(s + 7) * D], a7);
    }
    g_wpart[(b * SCHUNKS + chunk) * D2 + e] =
        ((a0 + a1) + (a2 + a3)) + ((a4 + a5) + (a6 + a7));
}

// ---------------------------------------------------------------------------
// Final: wcat = sum of partials; output = wcat @ Wv + bv
// ---------------------------------------------------------------------------
__global__ __launch_bounds__(512) void out_kernel(const float* __restrict__ wv_w,
                                                  const float* __restrict__ wv_b,
                                                  float* __restrict__ out) {
    __shared__ float wc[D2];
    const int b = blockIdx.x;
    const int e = threadIdx.x;
    float a = 0.f;
#pragma unroll
    for (int c = 0; c < SCHUNKS; c++) a += g_wpart[(b * SCHUNKS + c) * D2 + e];
    wc[e] = a;
    __syncthreads();
    float o = wv_b[e];
#pragma unroll 4
    for (int f = 0; f < D2; f++) o = fmaf(wc[f], wv_w[f * D2 + e], o);
    out[b * D2 + e] = o;
}

// ---------------------------------------------------------------------------
extern "C" void kernel_launch(void* const* d_in, const int* in_sizes, int n_in,
                              void* d_out, int out_size) {
    const float* au   = (const float*)d_in[0];
    const float* vi   = (const float*)d_in[1];
    const float* wq_w = (const float*)d_in[2];
    const float* wq_b = (const float*)d_in[3];
    const float* wk_w = (const float*)d_in[4];
    const float* wk_b = (const float*)d_in[5];
    const float* wv_w = (const float*)d_in[6];
    const float* wv_b = (const float*)d_in[7];
    float* out = (float*)d_out;

    static int smem_set = 0;
    if (!smem_set) {
        cudaFuncSetAttribute(score_kernel, cudaFuncAttributeMaxDynamicSharedMemorySize,
                             DSMEM_BYTES);
        smem_set = 1;
    }

    prep_M<<<dim3(16, 16), dim3(16, 16)>>>(wq_w, wk_w);
    prep_vec<<<1, 256>>>(wq_w, wq_b, wk_w, wk_b);
    score_kernel<<<NTOK / MTILE, 512, DSMEM_BYTES>>>(vi, au);
    softmax_kernel<<<B, 1024>>>(out);
    wsum_kernel<<<dim3(SCHUNKS, B), D2>>>(vi, au, out);
    out_kernel<<<B, D2>>>(wv_w, wv_b, out);
}

// round 7
// speedup vs baseline: 1.8932x; 1.1602x over previous
#include <cuda_runtime.h>
#include <cuda_fp16.h>
#include <math_constants.h>
#include <cstdint>

// Problem constants
#define B 16
#define S 8192
#define D 256
#define D2 512
#define NTOK (B * S)          // 131072 tokens
#define MTILE 128             // tokens per score CTA
#define SCHUNKS 8
#define SCHUNK (S / SCHUNKS)  // 1024

// ---------------------------------------------------------------------------
// Device scratch
// ---------------------------------------------------------------------------
// B operand = M^T as fp16 hi + fp16 residual, n-major (row n: k=0..255)
__device__ __align__(16) __half g_Bhi[D * D];
__device__ __align__(16) __half g_Blo[D * D];
__device__ float g_vec[2 * D + 1];      // c1[256], c2[256], c0
__device__ float g_score[NTOK];
__device__ float g_wpart[B * SCHUNKS * D2];
// d_out layout: [output: B*2D][weights: B*S]

// ---------------------------------------------------------------------------
// Helpers
// ---------------------------------------------------------------------------
__device__ __forceinline__ uint32_t smem_u32(const void* p) {
    uint32_t a;
    asm("{ .reg .u64 t; cvta.to.shared.u64 t, %1; cvt.u32.u64 %0, t; }"
        : "=r"(a) : "l"(p));
    return a;
}
__device__ __forceinline__ void ldsm_x4(uint32_t* r, uint32_t addr) {
    asm volatile("ldmatrix.sync.aligned.m8n8.x4.shared.b16 {%0,%1,%2,%3}, [%4];"
                 : "=r"(r[0]), "=r"(r[1]), "=r"(r[2]), "=r"(r[3]) : "r"(addr));
}
__device__ __forceinline__ void mma16816(float* d, const uint32_t* a,
                                         uint32_t b0, uint32_t b1) {
    asm volatile(
        "mma.sync.aligned.m16n8k16.row.col.f32.f16.f16.f32 "
        "{%0,%1,%2,%3}, {%4,%5,%6,%7}, {%8,%9}, {%0,%1,%2,%3};"
        : "+f"(d[0]), "+f"(d[1]), "+f"(d[2]), "+f"(d[3])
        : "r"(a[0]), "r"(a[1]), "r"(a[2]), "r"(a[3]), "r"(b0), "r"(b1));
}

// ---------------------------------------------------------------------------
// Prep 1: Bmat[n][k] = M[k][n] = Wq[k,:]·Wk[n,:]  -> fp16 hi + residual, n-major
// ---------------------------------------------------------------------------
__global__ void prep_M(const float* __restrict__ wq, const float* __restrict__ wk) {
    __shared__ float aS[16][16];
    __shared__ float bS[16][17];
    int tx = threadIdx.x, ty = threadIdx.y;
    int i = blockIdx.y * 16 + ty;   // k index
    int j = blockIdx.x * 16 + tx;   // n index
    float acc = 0.f;
    for (int kt = 0; kt < D; kt += 16) {
        aS[ty][tx] = wq[(blockIdx.y * 16 + ty) * D + kt + tx];
        bS[ty][tx] = wk[(blockIdx.x * 16 + ty) * D + kt + tx];
        __syncthreads();
#pragma unroll
        for (int kk = 0; kk < 16; kk++)
            acc = fmaf(aS[ty][kk], bS[tx][kk], acc);
        __syncthreads();
    }
    __half hi = __float2half_rn(acc);
    __half lo = __float2half_rn(acc - __half2float(hi));
    g_Bhi[j * D + i] = hi;
    g_Blo[j * D + i] = lo;
}

// ---------------------------------------------------------------------------
// Prep 2: c1[i] = Wq[i,:]·bk ; c2[i] = Wk[i,:]·bq ; c0 = bq·bk
// ---------------------------------------------------------------------------
__global__ void prep_vec(const float* __restrict__ wq, const float* __restrict__ bq,
                         const float* __restrict__ wk, const float* __restrict__ bk) {
    int i = threadIdx.x;
    float s1 = 0.f, s2 = 0.f;
    for (int k = 0; k < D; k++) {
        s1 = fmaf(wq[i * D + k], bk[k], s1);
        s2 = fmaf(wk[i * D + k], bq[k], s2);
    }
    g_vec[i] = s1;
    g_vec[D + i] = s2;
    if (i == 0) {
        float c0 = 0.f;
        for (int k = 0; k < D; k++) c0 = fmaf(bq[k], bk[k], c0);
        g_vec[2 * D] = c0;
    }
}

// ---------------------------------------------------------------------------
// Score kernel (mma.sync fp16, 2-product split): 128 tokens/CTA, 16 warps (4m x 4n).
// Warp (w&3, w>>2): m-rows 32*(w&3)..+31 (two m16 tiles), n-quarter 64*(w>>2).
// Dyn smem: A [128 x 528B]  B_hi [256 x 144B]  B_lo [256 x 144B]
// ---------------------------------------------------------------------------
#define A_PITCH 528
#define B_PITCH 144
#define SM_A 0
#define SM_BHI (128 * A_PITCH)            // 67584
#define SM_BLO (SM_BHI + 256 * B_PITCH)   // 104448
#define DSMEM_BYTES (SM_BLO + 256 * B_PITCH)  // 141312

__global__ __launch_bounds__(512, 1) void score_kernel(const float* __restrict__ vi,
                                                       const float* __restrict__ au) {
    extern __shared__ __align__(16) char dsm[];
    __shared__ float c1_s[D];
    __shared__ float c2_s[D];
    __shared__ float bpart[512];
    __shared__ float spart[4][128];

    const int tid = threadIdx.x;
    const int lane = tid & 31;
    const int w = tid >> 5;
    const int mbase = (w & 3) * 32;
    const int nq = w >> 2;                 // n-quarter 0..3
    const int tok0 = blockIdx.x * MTILE;
    const uint32_t sbase = smem_u32(dsm);

    if (tid < 256) {
        c1_s[tid] = g_vec[tid];
        c2_s[tid] = g_vec[D + tid];
    }
    __syncthreads();

    // ---- Convert vi tile to fp16 in smem; fold vi·c1 into bpart
    {
        const int r = tid >> 2;            // token row 0..127
        const int kb = (tid & 3) * 64;     // k-range start
        const float* vrow = vi + (size_t)(tok0 + r) * D + kb;
        char* da = dsm + SM_A + r * A_PITCH + kb * 2;
        float bs = 0.f;
#pragma unroll 2
        for (int k8 = 0; k8 < 64; k8 += 8) {
            float4 v0 = *(const float4*)(vrow + k8);
            float4 v1 = *(const float4*)(vrow + k8 + 4);
            float vv[8] = {v0.x, v0.y, v0.z, v0.w, v1.x, v1.y, v1.z, v1.w};
            uint32_t hw[4];
#pragma unroll
            for (int u = 0; u < 4; u++) {
                float a = vv[2 * u], bvl = vv[2 * u + 1];
                bs = fmaf(a, c1_s[kb + k8 + 2 * u], bs);
                bs = fmaf(bvl, c1_s[kb + k8 + 2 * u + 1], bs);
                __half2 hp;
                hp.x = __float2half_rn(a);
                hp.y = __float2half_rn(bvl);
                hw[u] = *(uint32_t*)&hp;
            }
            *(uint4*)(da + k8 * 2) = make_uint4(hw[0], hw[1], hw[2], hw[3]);
        }
        bpart[tid] = bs;
    }

    // ---- ldmatrix lane addressing
    const uint32_t a_lane = (uint32_t)((lane & 15) * A_PITCH + ((lane >> 4) << 4));
    const uint32_t aA = sbase + SM_A + mbase * A_PITCH + a_lane;
    // B x4: m0=(n0-7,k0-7) m1=(n0-7,k8-15) m2=(n8-15,k0-7) m3=(n8-15,k8-15)
    const uint32_t b_lane =
        (uint32_t)(((lane & 7) + ((lane >> 4) << 3)) * B_PITCH + ((lane & 8) ? 16 : 0));
    const uint32_t bH = sbase + SM_BHI + nq * 64 * B_PITCH + b_lane;
    const uint32_t bL = sbase + SM_BLO + nq * 64 * B_PITCH + b_lane;

    float acc[2][8][4] = {};

#pragma unroll 1
    for (int c = 0; c < 4; c++) {
        __syncthreads();   // prev chunk consumed (1st iter: A conversion visible)
        {   // stage B chunk: 256 n-rows x 64 k (128B) -> 144B pitch rows
            const int row = tid >> 1;
            const int half = tid & 1;
            const uint4* srcH = (const uint4*)(g_Bhi + row * D + c * 64 + half * 32);
            const uint4* srcL = (const uint4*)(g_Blo + row * D + c * 64 + half * 32);
            uint4* dH = (uint4*)(dsm + SM_BHI + row * B_PITCH + half * 64);
            uint4* dL = (uint4*)(dsm + SM_BLO + row * B_PITCH + half * 64);
#pragma unroll
            for (int q = 0; q < 4; q++) { dH[q] = srcH[q]; dL[q] = srcL[q]; }
        }
        __syncthreads();

#pragma unroll
        for (int ks = 0; ks < 4; ks++) {
            const uint32_t ka = (uint32_t)((c * 64 + ks * 16) * 2);  // A byte off
            const uint32_t kb2 = (uint32_t)(ks * 32);                // B byte off
            uint32_t ah[2][4];
            ldsm_x4(ah[0], aA + ka);
            ldsm_x4(ah[1], aA + 16 * A_PITCH + ka);
#pragma unroll
            for (int nt2 = 0; nt2 < 4; nt2++) {
                const uint32_t bo = (uint32_t)(nt2 * 16 * B_PITCH) + kb2;
                uint32_t bh4[4], bl4[4];
                ldsm_x4(bh4, bH + bo);
                ldsm_x4(bl4, bL + bo);
#pragma unroll
                for (int sub = 0; sub < 2; sub++) {
                    const int nt = nt2 * 2 + sub;
                    const uint32_t b0h = bh4[2 * sub], b1h = bh4[2 * sub + 1];
                    const uint32_t b0l = bl4[2 * sub], b1l = bl4[2 * sub + 1];
#pragma unroll
                    for (int mt = 0; mt < 2; mt++) {
                        mma16816(acc[mt][nt], ah[mt], b0h, b1h);
                        mma16816(acc[mt][nt], ah[mt], b0l, b1l);
                    }
                }
            }
        }
    }

    // ---- Epilogue: part[t] = sum_n (Q'[t][n]+c2[n]) * au[t][n]
    float prow[2][2] = {};
#pragma unroll
    for (int mt = 0; mt < 2; mt++) {
        const float* au0 = au + (size_t)(tok0 + mbase + mt * 16 + (lane >> 2)) * D;
        const float* au1 = au0 + 8 * D;
#pragma unroll
        for (int nt = 0; nt < 8; nt++) {
            const int n = nq * 64 + nt * 8 + (lane & 3) * 2;
            const float2 c2v = *(const float2*)&c2_s[n];
            const float2 x0 = __ldg((const float2*)(au0 + n));
            const float2 x1 = __ldg((const float2*)(au1 + n));
            prow[mt][0] = fmaf(acc[mt][nt][0] + c2v.x, x0.x, prow[mt][0]);
            prow[mt][0] = fmaf(acc[mt][nt][1] + c2v.y, x0.y, prow[mt][0]);
            prow[mt][1] = fmaf(acc[mt][nt][2] + c2v.x, x1.x, prow[mt][1]);
            prow[mt][1] = fmaf(acc[mt][nt][3] + c2v.y, x1.y, prow[mt][1]);
        }
    }
#pragma unroll
    for (int mt = 0; mt < 2; mt++)
#pragma unroll
        for (int j = 0; j < 2; j++) {
            float v = prow[mt][j];
            v += __shfl_xor_sync(0xffffffffu, v, 1);
            v += __shfl_xor_sync(0xffffffffu, v, 2);
            if ((lane & 3) == 0)
                spart[nq][mbase + mt * 16 + j * 8 + (lane >> 2)] = v;
        }
    __syncthreads();

    if (tid < 128) {
        const float c0 = g_vec[2 * D];
        float s = spart[0][tid] + spart[1][tid] + spart[2][tid] + spart[3][tid]
                + ((bpart[4 * tid] + bpart[4 * tid + 1])
                   + (bpart[4 * tid + 2] + bpart[4 * tid + 3]))
                + c0;
        g_score[tok0 + tid] = s * 0.0625f;   // 1/sqrt(256)
    }
}

// ---------------------------------------------------------------------------
// Softmax over S per batch; writes weights into d_out (after output section).
// ---------------------------------------------------------------------------
__global__ __launch_bounds__(1024) void softmax_kernel(float* __restrict__ out) {
    __shared__ float red[32];
    __shared__ float sh_val;
    const int b = blockIdx.x;
    const int tid = threadIdx.x;
    const int lane = tid & 31, warp = tid >> 5;
    const float* sc = g_score + b * S;
    float* w = out + B * D2 + b * S;

    float v[8];
    float mx = -CUDART_INF_F;
#pragma unroll
    for (int i = 0; i < 8; i++) {
        v[i] = sc[tid + i * 1024];
        mx = fmaxf(mx, v[i]);
    }
#pragma unroll
    for (int o = 16; o > 0; o >>= 1) mx = fmaxf(mx, __shfl_xor_sync(0xffffffffu, mx, o));
    if (lane == 0) red[warp] = mx;
    __syncthreads();
    if (warp == 0) {
        float m = red[lane];
#pragma unroll
        for (int o = 16; o > 0; o >>= 1) m = fmaxf(m, __shfl_xor_sync(0xffffffffu, m, o));
        if (lane == 0) sh_val = m;
    }
    __syncthreads();
    mx = sh_val;

    float sum = 0.f;
#pragma unroll
    for (int i = 0; i < 8; i++) {
        v[i] = expf(v[i] - mx);
        sum += v[i];
    }
#pragma unroll
    for (int o = 16; o > 0; o >>= 1) sum += __shfl_xor_sync(0xffffffffu, sum, o);
    if (lane == 0) red[warp] = sum;
    __syncthreads();
    if (warp == 0) {
        float s2 = red[lane];
#pragma unroll
        for (int o = 16; o > 0; o >>= 1) s2 += __shfl_xor_sync(0xffffffffu, s2, o);
        if (lane == 0) sh_val = s2;
    }
    __syncthreads();
    const float inv = 1.f / sh_val;
#pragma unroll
    for (int i = 0; i < 8; i++) w[tid + i * 1024] = v[i] * inv;
}

// ---------------------------------------------------------------------------
// Weighted sum of cat(vi, au): partial over S-chunks
// ---------------------------------------------------------------------------
__global__ __launch_bounds__(512) void wsum_kernel(const float* __restrict__ vi,
                                                   const float* __restrict__ au,
                                                   const float* __restrict__ out) {
    const int chunk = blockIdx.x;
    const int b = blockIdx.y;
    const int e = threadIdx.x;  // 0..511
    const float* w = out + B * D2 + b * S + chunk * SCHUNK;
    const float* src = (e < D) ? (vi + ((long)b * S + chunk * SCHUNK) * D + e)
                               : (au + ((long)b * S + chunk * SCHUNK) * D + (e - D));
    float a0 = 0.f, a1 = 0.f, a2 = 0.f, a3 = 0.f;
    float a4 = 0.f, a5 = 0.f, a6 = 0.f, a7 = 0.f;
#pragma unroll 1
    for (int s = 0; s < SCHUNK; s += 8) {
        a0 = fmaf(w[s + 0], src[(s + 0) * D], a0);
        a1 = fmaf(w[s + 1], src[(s + 1) * D], a1);
        a2 = fmaf(w[s + 2], src[(s + 2) * D], a2);
        a3 = fmaf(w[s + 3], src[(s + 3) * D], a3);
        a4 = fmaf(w[s + 4], src[(s + 4) * D], a4);
        a5 = fmaf(w[s + 5], src[(s + 5) * D], a5);
        a6 = fmaf(w[s + 6], src[(s + 6) * D], a6);
        a7 = fmaf(w[s + 7], src[(s + 7) * D], a7);
    }
    g_wpart[(b * SCHUNKS + chunk) * D2 + e] =
        ((a0 + a1) + (a2 + a3)) + ((a4 + a5) + (a6 + a7));
}

// ---------------------------------------------------------------------------
// Final: wcat = sum of partials; output = wcat @ Wv + bv
// ---------------------------------------------------------------------------
__global__ __launch_bounds__(512) void out_kernel(const float* __restrict__ wv_w,
                                                  const float* __restrict__ wv_b,
                                                  float* __restrict__ out) {
    __shared__ float wc[D2];
    const int b = blockIdx.x;
    const int e = threadIdx.x;
    float a = 0.f;
#pragma unroll
    for (int c = 0; c < SCHUNKS; c++) a += g_wpart[(b * SCHUNKS + c) * D2 + e];
    wc[e] = a;
    __syncthreads();
    float o = wv_b[e];
#pragma unroll 4
    for (int f = 0; f < D2; f++) o = fmaf(wc[f], wv_w[f * D2 + e], o);
    out[b * D2 + e] = o;
}

// ---------------------------------------------------------------------------
extern "C" void kernel_launch(void* const* d_in, const int* in_sizes, int n_in,
                              void* d_out, int out_size) {
    const float* au   = (const float*)d_in[0];
    const float* vi   = (const float*)d_in[1];
    const float* wq_w = (const float*)d_in[2];
    const float* wq_b = (const float*)d_in[3];
    const float* wk_w = (const float*)d_in[4];
    const float* wk_b = (const float*)d_in[5];
    const float* wv_w = (const float*)d_in[6];
    const float* wv_b = (const float*)d_in[7];
    float* out = (float*)d_out;

    static int smem_set = 0;
    if (!smem_set) {
        cudaFuncSetAttribute(score_kernel, cudaFuncAttributeMaxDynamicSharedMemorySize,
                             DSMEM_BYTES);
        smem_set = 1;
    }

    prep_M<<<dim3(16, 16), dim3(16, 16)>>>(wq_w, wk_w);
    prep_vec<<<1, 256>>>(wq_w, wq_b, wk_w, wk_b);
    score_kernel<<<NTOK / MTILE, 512, DSMEM_BYTES>>>(vi, au);
    softmax_kernel<<<B, 1024>>>(out);
    wsum_kernel<<<dim3(SCHUNKS, B), D2>>>(vi, au, out);
    out_kernel<<<B, D2>>>(wv_w, wv_b, out);
}